// round 8
// baseline (speedup 1.0000x reference)
#include <cuda_runtime.h>
#include <cuda_bf16.h>
#include <cstdint>

#define DD 64
#define KC 512
#define ROWSB 128
#define NTHR 512          // 16 warps: warp = (subpartition rows, code quarter)
#define NCTA 148
#define NSLOT 24
#define MARGIN 5e-3f

#if defined(__CUDA_ARCH__) && (defined(__CUDA_ARCH_FEAT_SM103_ALL) || defined(__CUDA_ARCH_FEAT_SM100_ALL) || defined(__CUDA_ARCH_FEAT_SM101_ALL))
#define HAS_TCGEN05 1
#else
#define HAS_TCGEN05 0
#endif

// ---- smem byte offsets ----
#define MB_MDONE   0
#define TMEM_SLOT  16
#define CS_OFF     128                 // 512 f32
#define XS_OFF     2176                // 2 x 128 f32
#define BD_OFF     3200                // 4 x 128 f32
#define BI_OFF     5248                // 4 x 128 int
#define SIDX_OFF   7296                // 128 int
#define A_OFF(b)   (8192 + (b) * 16384)
#define B_OFF      40960               // 64KB bf16 h-limb, SW128 (1024-aligned)
#define STK_OFF    106496              // 16 warps x 24 slots x 32 lanes x 8B = 96KB
#define SMEM_TOTAL 204800

__device__ __forceinline__ uint32_t smem_u32(const void* p) {
    uint32_t a;
    asm("{ .reg .u64 t; cvta.to.shared.u64 t, %1; cvt.u32.u64 %0, t; }" : "=r"(a) : "l"(p));
    return a;
}
__device__ __forceinline__ uint32_t sw128(uint32_t off) { return off ^ ((off >> 3) & 0x70); }

#if HAS_TCGEN05
__device__ __forceinline__ uint32_t elect1() {
    uint32_t p;
    asm volatile("{ .reg .pred p; elect.sync _|p, 0xFFFFFFFF; selp.b32 %0, 1, 0, p; }" : "=r"(p));
    return p;
}
__device__ __forceinline__ void mbar_init(uint32_t a, uint32_t cnt) {
    asm volatile("mbarrier.init.shared.b64 [%0], %1;" :: "r"(a), "r"(cnt) : "memory");
}
__device__ __forceinline__ void mbar_wait(uint32_t a, uint32_t parity) {
    asm volatile(
        "{\n\t.reg .pred P;\n"
        "WL_%=:\n\t"
        "mbarrier.try_wait.parity.acquire.cta.shared::cta.b64 P, [%0], %1, 0x989680;\n\t"
        "@!P bra WL_%=;\n\t}"
        :: "r"(a), "r"(parity) : "memory");
}
__device__ __forceinline__ void fence_async() {
    asm volatile("fence.proxy.async.shared::cta;" ::: "memory");
}
__device__ __forceinline__ void tmem_alloc(uint32_t slot, uint32_t ncols) {
    asm volatile("tcgen05.alloc.cta_group::1.sync.aligned.shared::cta.b32 [%0], %1;"
                 :: "r"(slot), "r"(ncols) : "memory");
}
__device__ __forceinline__ void tmem_dealloc(uint32_t base, uint32_t ncols) {
    asm volatile("tcgen05.dealloc.cta_group::1.sync.aligned.b32 %0, %1;" :: "r"(base), "r"(ncols));
}
__device__ __forceinline__ void mma_f16_ss(uint32_t d, uint64_t ad, uint64_t bd,
                                           uint32_t idesc, uint32_t en) {
    asm volatile(
        "{\n\t.reg .pred p;\n\t"
        "setp.ne.u32 p, %5, 0;\n\t"
        "tcgen05.mma.cta_group::1.kind::f16 [%0], %1, %2, %3, {%4, %4, %4, %4}, p;\n\t}"
        :: "r"(d), "l"(ad), "l"(bd), "r"(idesc), "r"(0u), "r"(en) : "memory");
}
__device__ __forceinline__ void mma_commit(uint32_t mbar) {
    asm volatile("tcgen05.commit.cta_group::1.mbarrier::arrive::one.shared::cluster.b64 [%0];"
                 :: "r"(mbar) : "memory");
}
__device__ __forceinline__ void fence_tc_after() {
    asm volatile("tcgen05.fence::after_thread_sync;" ::: "memory");
}
__device__ __forceinline__ void fence_tc_before() {
    asm volatile("tcgen05.fence::before_thread_sync;" ::: "memory");
}
#define LDTM_X32(r, a) \
    asm volatile("tcgen05.ld.sync.aligned.32x32b.x32.b32 " \
        "{%0,%1,%2,%3,%4,%5,%6,%7,%8,%9,%10,%11,%12,%13,%14,%15," \
        "%16,%17,%18,%19,%20,%21,%22,%23,%24,%25,%26,%27,%28,%29,%30,%31}, [%32];" \
        : "=r"((r)[0]),"=r"((r)[1]),"=r"((r)[2]),"=r"((r)[3]),"=r"((r)[4]),"=r"((r)[5]), \
          "=r"((r)[6]),"=r"((r)[7]),"=r"((r)[8]),"=r"((r)[9]),"=r"((r)[10]),"=r"((r)[11]), \
          "=r"((r)[12]),"=r"((r)[13]),"=r"((r)[14]),"=r"((r)[15]),"=r"((r)[16]),"=r"((r)[17]), \
          "=r"((r)[18]),"=r"((r)[19]),"=r"((r)[20]),"=r"((r)[21]),"=r"((r)[22]),"=r"((r)[23]), \
          "=r"((r)[24]),"=r"((r)[25]),"=r"((r)[26]),"=r"((r)[27]),"=r"((r)[28]),"=r"((r)[29]), \
          "=r"((r)[30]),"=r"((r)[31]) : "r"(a))
__device__ __forceinline__ void tmem_wait_ld() {
    asm volatile("tcgen05.wait::ld.sync.aligned;" ::: "memory");
}
#endif

#define DESC_BASE 0x4000404000010000ULL
__device__ __forceinline__ uint64_t mk_desc(uint32_t addr) {
    return DESC_BASE | ((uint64_t)(addr >> 4) & 0x3FFF);
}
#define IDESC 0x8200490u   // f32 acc, bf16 a/b, M=128, N=128 (proven R3-R7)

__device__ __forceinline__ uint32_t packbf(float a, float b) {
    return (uint32_t)__bfloat16_as_ushort(__float2bfloat16(a)) |
           ((uint32_t)__bfloat16_as_ushort(__float2bfloat16(b)) << 16);
}

__global__ void __launch_bounds__(NTHR, 1)
vq_persist(const float* __restrict__ x, const float* __restrict__ cbk,
           float* __restrict__ out, int n) {
    extern __shared__ char smem[];
    const int tid = threadIdx.x;
    const int bid = blockIdx.x;
    const size_t nD = (size_t)n * DD;
    float* Cs = (float*)(smem + CS_OFF);

#if HAS_TCGEN05
    const uint32_t sb = smem_u32(smem);
    const int wid = tid >> 5;
    const int lane = tid & 31;
    float* XsS = (float*)(smem + XS_OFF);
    float* BD = (float*)(smem + BD_OFF);
    int* BI = (int*)(smem + BI_OFF);
    int* sidx = (int*)(smem + SIDX_OFF);

    const int ntiles = (n + ROWSB - 1) / ROWSB;
    const int nt = (ntiles > bid) ? (ntiles - bid + NCTA - 1) / NCTA : 0;

    // ---------- startup ----------
    if (tid == 0) mbar_init(sb + MB_MDONE, 1);
    if (wid == 0) tmem_alloc(sb + TMEM_SLOT, 512);

    // B h-limb: 512x64 -> bf16 SW128 (128B per code row)
    for (int i = tid; i < KC * DD / 4; i += NTHR) {
        int code = i >> 4, kq = i & 15;
        float4 v = __ldg(((const float4*)cbk) + i);
        uint64_t u = (uint64_t)packbf(v.x, v.y) | ((uint64_t)packbf(v.z, v.w) << 32);
        *(uint64_t*)(smem + B_OFF + sw128(code * 128 + kq * 8)) = u;
    }
    // exact csq (reference rounding order)
    for (int c = tid; c < KC; c += NTHR) {
        float s = 0.0f;
        const float* cr = cbk + c * DD;
        for (int k = 0; k < DD; ++k) {
            float v = __ldg(cr + k);
            s = __fadd_rn(s, __fmul_rn(v, v));
        }
        Cs[c] = s;
    }
    // build A[0] for tile 0
    if (tid < 128 && nt > 0) {
        const int grow = bid * ROWSB + tid;
        float4 f[16];
        if (grow < n) {
            const float4* xr = (const float4*)(x + (size_t)grow * DD);
            #pragma unroll
            for (int k4 = 0; k4 < 16; ++k4) f[k4] = __ldg(xr + k4);
        } else {
            #pragma unroll
            for (int k4 = 0; k4 < 16; ++k4) f[k4] = make_float4(0.f, 0.f, 0.f, 0.f);
        }
        float s = 0.0f;
        #pragma unroll
        for (int k4 = 0; k4 < 16; ++k4) {
            s = __fadd_rn(s, __fmul_rn(f[k4].x, f[k4].x));
            s = __fadd_rn(s, __fmul_rn(f[k4].y, f[k4].y));
            s = __fadd_rn(s, __fmul_rn(f[k4].z, f[k4].z));
            s = __fadd_rn(s, __fmul_rn(f[k4].w, f[k4].w));
        }
        XsS[tid] = s;
        #pragma unroll
        for (int c8 = 0; c8 < 8; ++c8) {
            float4 a = f[c8 * 2], b = f[c8 * 2 + 1];
            uint4 u;
            u.x = packbf(a.x, a.y); u.y = packbf(a.z, a.w);
            u.z = packbf(b.x, b.y); u.w = packbf(b.z, b.w);
            *(uint4*)(smem + A_OFF(0) + sw128(tid * 128 + c8 * 16)) = u;
        }
    }
    fence_async();
    __syncthreads();
    const uint32_t tmem = *(volatile uint32_t*)(smem + TMEM_SLOT);

    const int sub = wid & 3;
    const int wg = wid >> 2;              // code quarter
    const int srow = sub * 32 + lane;
    const int cbase = wg * 128;
    const uint64_t bdesc = mk_desc(sb + B_OFF);
    const uint32_t stk = sb + STK_OFF + wid * (NSLOT * 32 * 8) + lane * 8;
    const uint32_t stkoff_c = STK_OFF + wid * (NSLOT * 32 * 8) + lane * 8;

    // ---------- main loop ----------
    for (int it = 0; it < nt; ++it) {
        const int buf = it & 1;
        const int tile = bid + it * NCTA;

        // 1) issue MMAs (TMEM WAR safe: prev iter's LDTM done before prev sync)
        if (wid == 0) {
            if (elect1()) {
                const uint64_t adesc = mk_desc(sb + A_OFF(buf));
                for (int q = 0; q < 4; ++q) {
                    const uint64_t bq = bdesc + (uint32_t)(q * 1024);
                    const uint32_t dcol = tmem + q * 128;
                    #pragma unroll
                    for (int k = 0; k < 4; ++k)
                        mma_f16_ss(dcol, adesc + k * 2, bq + k * 2, IDESC, k != 0);
                }
                mma_commit(sb + MB_MDONE);
            }
        }

        // 2) build A[buf^1] for tile it+1 (overlaps MMA)
        if (tid < 128 && it + 1 < nt) {
            const int grow2 = (bid + (it + 1) * NCTA) * ROWSB + tid;
            float4 f[16];
            if (grow2 < n) {
                const float4* xr = (const float4*)(x + (size_t)grow2 * DD);
                #pragma unroll
                for (int k4 = 0; k4 < 16; ++k4) f[k4] = __ldg(xr + k4);
            } else {
                #pragma unroll
                for (int k4 = 0; k4 < 16; ++k4) f[k4] = make_float4(0.f, 0.f, 0.f, 0.f);
            }
            float s = 0.0f;
            #pragma unroll
            for (int k4 = 0; k4 < 16; ++k4) {
                s = __fadd_rn(s, __fmul_rn(f[k4].x, f[k4].x));
                s = __fadd_rn(s, __fmul_rn(f[k4].y, f[k4].y));
                s = __fadd_rn(s, __fmul_rn(f[k4].z, f[k4].z));
                s = __fadd_rn(s, __fmul_rn(f[k4].w, f[k4].w));
            }
            XsS[(buf ^ 1) * 128 + tid] = s;
            #pragma unroll
            for (int c8 = 0; c8 < 8; ++c8) {
                float4 a = f[c8 * 2], b = f[c8 * 2 + 1];
                uint4 u;
                u.x = packbf(a.x, a.y); u.y = packbf(a.z, a.w);
                u.z = packbf(b.x, b.y); u.w = packbf(b.z, b.w);
                *(uint4*)(smem + A_OFF(buf ^ 1) + sw128(tid * 128 + c8 * 16)) = u;
            }
            fence_async();
        }

        // 3) wait MMA (normally already complete)
        mbar_wait(sb + MB_MDONE, (uint32_t)(it & 1));
        fence_tc_after();

        // 4) branch-free filter scan over this thread's (row, 128-code quarter).
        //    Ranking key: csq - 2*dot (xs is row-constant -> dropped; offsets cancel).
        float thr = 3.4e38f;
        int cnt = 0;
        for (int b = 0; b < 4; ++b) {
            uint32_t rg[32];
            LDTM_X32(rg, tmem + cbase + b * 32);
            tmem_wait_ld();
            const int base = cbase + b * 32;
            #pragma unroll
            for (int j4 = 0; j4 < 8; ++j4) {
                float4 cs4 = *(const float4*)(Cs + base + j4 * 4);
                #pragma unroll
                for (int jj = 0; jj < 4; ++jj) {
                    const int j = j4 * 4 + jj;
                    float csv = (jj == 0) ? cs4.x : (jj == 1) ? cs4.y : (jj == 2) ? cs4.z : cs4.w;
                    float dist = __fmaf_rn(-2.0f, __uint_as_float(rg[j]), csv);
                    uint32_t addr = stk + (uint32_t)(min(cnt, NSLOT - 1) << 8);
                    // predicated insert: no branch, no BSSY, smem write only when kept
                    asm volatile(
                        "{\n\t.reg .pred p;\n\t"
                        "setp.le.f32 p, %1, %2;\n\t"
                        "@p st.shared.v2.b32 [%3], {%4, %5};\n\t"
                        "@p add.s32 %0, %0, 1;\n\t}"
                        : "+r"(cnt)
                        : "f"(dist), "f"(thr), "r"(addr),
                          "r"(__float_as_int(dist)), "r"(base + j)
                        : "memory");
                    thr = fminf(thr, dist + MARGIN);
                }
            }
        }

        // 5) exact refine of pruned candidates (thr is now final_min + MARGIN)
        const int grow = tile * ROWSB + srow;
        float best = 3.4e38f; int bi = 0x7FFFFFFF;
        if (grow < n) {
            const float xs = XsS[buf * 128 + srow];
            const float4* xr = (const float4*)(x + (size_t)grow * DD);
            if (cnt > NSLOT) {
                // overflow fallback (P ~ 0): exact scan of this quarter's 128 codes
                for (int code = cbase; code < cbase + 128; ++code) {
                    const float4* cr = (const float4*)(cbk + code * DD);
                    float dot = 0.0f;
                    #pragma unroll
                    for (int k4 = 0; k4 < 16; ++k4) {
                        float4 a = __ldg(xr + k4);
                        float4 b2 = __ldg(cr + k4);
                        dot = __fmaf_rn(a.x, b2.x, dot);
                        dot = __fmaf_rn(a.y, b2.y, dot);
                        dot = __fmaf_rn(a.z, b2.z, dot);
                        dot = __fmaf_rn(a.w, b2.w, dot);
                    }
                    float d = __fmaf_rn(-2.0f, dot, __fadd_rn(xs, Cs[code]));
                    if (d < best || (d == best && code < bi)) { best = d; bi = code; }
                }
            } else {
                for (int i = 0; i < cnt; ++i) {
                    float2 e = *(const float2*)(smem + stkoff_c + i * 256);
                    if (e.x <= thr) {
                        const int code = __float_as_int(e.y);
                        const float4* cr = (const float4*)(cbk + code * DD);
                        float dot = 0.0f;
                        #pragma unroll
                        for (int k4 = 0; k4 < 16; ++k4) {
                            float4 a = __ldg(xr + k4);
                            float4 b2 = __ldg(cr + k4);
                            dot = __fmaf_rn(a.x, b2.x, dot);
                            dot = __fmaf_rn(a.y, b2.y, dot);
                            dot = __fmaf_rn(a.z, b2.z, dot);
                            dot = __fmaf_rn(a.w, b2.w, dot);
                        }
                        float t = __fadd_rn(xs, Cs[code]);
                        float d = __fmaf_rn(-2.0f, dot, t);
                        if (d < best || (d == best && code < bi)) { best = d; bi = code; }
                    }
                }
            }
        }
        BD[wg * 128 + srow] = best;
        BI[wg * 128 + srow] = bi;

        fence_tc_before();
        __syncthreads();

        // 6) merge 4 quarters (ascending quarter + strict < == lowest-index ties)
        if (tid < 128) {
            float bd = BD[tid]; int bib = BI[tid];
            #pragma unroll
            for (int g = 1; g < 4; ++g) {
                float d = BD[g * 128 + tid]; int ii = BI[g * 128 + tid];
                if (d < bd || (d == bd && ii < bib)) { bd = d; bib = ii; }
            }
            sidx[tid] = bib;
            const int g = tile * ROWSB + tid;
            if (g < n) out[2 * nD + g] = (float)bib;
        }
        __syncthreads();

        // 7) gather z_q_x / z_q_x_bar
        for (int i = tid; i < ROWSB * 32; i += NTHR) {
            const int row = i >> 5;
            const int d = (i >> 4) & 1;
            const int q = i & 15;
            const int g = tile * ROWSB + row;
            if (g < n) {
                float4 v = __ldg(((const float4*)cbk) + sidx[row] * 16 + q);
                ((float4*)(out + (size_t)d * nD + (size_t)g * DD))[q] = v;
            }
        }
    }

    __syncthreads();
    if (wid == 0) tmem_dealloc(tmem, 512);

#else
    // ============ generic-arch fallback (compile-only on GB300) ============
    for (int c = tid; c < KC; c += NTHR) {
        float s = 0.0f;
        const float* cr = cbk + c * DD;
        for (int k = 0; k < DD; ++k) {
            float v = cr[k];
            s = __fadd_rn(s, __fmul_rn(v, v));
        }
        Cs[c] = s;
    }
    __syncthreads();
    for (long long row = (long long)bid * NTHR + tid; row < n; row += (long long)gridDim.x * NTHR) {
        const float* xr = x + row * DD;
        float xv[DD];
        for (int k = 0; k < DD; ++k) xv[k] = xr[k];
        float xs = 0.0f;
        for (int k = 0; k < DD; ++k) xs = __fadd_rn(xs, __fmul_rn(xv[k], xv[k]));
        float best = 3.4e38f; int bi = 0;
        for (int c = 0; c < KC; ++c) {
            const float* cr = cbk + c * DD;
            float dot = 0.0f;
            for (int k = 0; k < DD; ++k) dot = __fmaf_rn(xv[k], cr[k], dot);
            float d = __fmaf_rn(-2.0f, dot, __fadd_rn(xs, Cs[c]));
            if (d < best) { best = d; bi = c; }
        }
        out[2 * nD + row] = (float)bi;
        const float* cr = cbk + bi * DD;
        for (int k = 0; k < DD; ++k) {
            out[(size_t)row * DD + k] = cr[k];
            out[nD + (size_t)row * DD + k] = cr[k];
        }
    }
#endif
}

extern "C" void kernel_launch(void* const* d_in, const int* in_sizes, int n_in,
                              void* d_out, int out_size) {
    const float* x = (const float*)d_in[0];
    const float* cbk = (const float*)d_in[1];
    float* out = (float*)d_out;
    const int n = in_sizes[0] / DD;

    cudaFuncSetAttribute(vq_persist, cudaFuncAttributeMaxDynamicSharedMemorySize, SMEM_TOTAL);
    vq_persist<<<NCTA, NTHR, SMEM_TOTAL>>>(x, cbk, out, n);
}